// round 17
// baseline (speedup 1.0000x reference)
#include <cuda_runtime.h>
#include <cuda_fp16.h>
#include <cstdint>
#include <math.h>

#define Bn 4
#define Tn 2048
#define En 1024
#define Hn 16
#define HSn 64
#define Mn (Bn * Tn)   // 8192

// Scratch buffers (device globals: allocation-free rule). fp16 everywhere.
__device__ __half g_xh[Mn * En];
__device__ __half g_wk[En * En];
__device__ __half g_wq[En * En];
__device__ __half g_wv[En * En];
__device__ __half g_wo[En * En];
__device__ __half g_k[Mn * En];
__device__ __half g_q[Mn * En];
__device__ __half g_v[Mn * En];
__device__ __half g_att[Mn * En];

__device__ __forceinline__ void mma_f16(float* c, const unsigned* a, const unsigned* b) {
    asm volatile(
        "mma.sync.aligned.m16n8k16.row.col.f32.f16.f16.f32 "
        "{%0,%1,%2,%3}, {%4,%5,%6,%7}, {%8,%9}, {%0,%1,%2,%3};"
        : "+f"(c[0]), "+f"(c[1]), "+f"(c[2]), "+f"(c[3])
        : "r"(a[0]), "r"(a[1]), "r"(a[2]), "r"(a[3]), "r"(b[0]), "r"(b[1]));
}
__device__ __forceinline__ void ldm_x4(unsigned* r, unsigned a) {
    asm volatile("ldmatrix.sync.aligned.m8n8.x4.shared.b16 {%0,%1,%2,%3}, [%4];"
                 : "=r"(r[0]), "=r"(r[1]), "=r"(r[2]), "=r"(r[3]) : "r"(a));
}
__device__ __forceinline__ void ldm_x4_t(unsigned* r, unsigned a) {
    asm volatile("ldmatrix.sync.aligned.m8n8.x4.trans.shared.b16 {%0,%1,%2,%3}, [%4];"
                 : "=r"(r[0]), "=r"(r[1]), "=r"(r[2]), "=r"(r[3]) : "r"(a));
}
__device__ __forceinline__ unsigned h2u(__half2 h) {
    return *reinterpret_cast<unsigned*>(&h);
}
__device__ __forceinline__ void cpa16(unsigned dst, const void* src) {
    asm volatile("cp.async.cg.shared.global [%0], [%1], 16;" :: "r"(dst), "l"(src));
}
__device__ __forceinline__ float ex2(float x) {   // raw MUFU.EX2 (fp32)
    float r;
    asm("ex2.approx.f32 %0, %1;" : "=f"(r) : "f"(x));
    return r;
}
__device__ __forceinline__ unsigned ex2h2(unsigned x) {  // packed fp16x2 exp2
    unsigned r;
    asm("ex2.approx.f16x2 %0, %1;" : "=r"(r) : "r"(x));
    return r;
}

// ---------------------------------------------------------------------------
// One-time fp32 -> fp16 conversion (single fused launch).
// blocks: [0,8192) x | [8192,9216) Wk*0.125*log2e | then Wq | Wv | Wo
// ---------------------------------------------------------------------------
__global__ void cvt_all(const float* __restrict__ x,
                        const float* __restrict__ wk, const float* __restrict__ wq,
                        const float* __restrict__ wv, const float* __restrict__ wo,
                        __half* __restrict__ xh,
                        __half* __restrict__ hk, __half* __restrict__ hq,
                        __half* __restrict__ hv, __half* __restrict__ ho) {
    int bid = blockIdx.x;
    const float* s;
    __half* d;
    float sc = 1.f;
    size_t base;
    if (bid < 8192)       { s = x;  d = xh; base = (size_t)bid * 1024; }
    else if (bid < 9216)  { s = wk; d = hk; base = (size_t)(bid - 8192) * 1024;
                            sc = 0.125f * 1.4426950408889634f; }
    else if (bid < 10240) { s = wq; d = hq; base = (size_t)(bid - 9216) * 1024; }
    else if (bid < 11264) { s = wv; d = hv; base = (size_t)(bid - 10240) * 1024; }
    else                  { s = wo; d = ho; base = (size_t)(bid - 11264) * 1024; }
    size_t i = base + (size_t)threadIdx.x * 4;
    float4 v = *(const float4*)(s + i);
    *(uint2*)(d + i) = make_uint2(h2u(__floats2half2_rn(v.x * sc, v.y * sc)),
                                  h2u(__floats2half2_rn(v.z * sc, v.w * sc)));
}

// ===========================================================================
// FP16 NT GEMM body: C[M,N] = A[M,K] @ Bm[N,K]^T, 64x128 tile, BK=64,
// 3-stage cp.async ring, ONE __syncthreads per k-iter, 3 CTAs/SM.
// smem row = 64 halves = 128B = 8 x 16B groups, swizzle phys = g ^ (row & 7).
// stage layout: A(64x64h = 8KB) | B(128x64h = 16KB), stage stride 24KB.
// 8 warps: wm = warp>>2 (M offset wm*32), wn = warp&3 (N offset wn*32).
// ===========================================================================
__device__ __forceinline__ void gemm_body(
    const __half* __restrict__ A, const __half* __restrict__ Bm,
    float acc[2][4][4], __half* sm, int m0, int n0) {
    const int tid = threadIdx.x, lane = tid & 31, warp = tid >> 5;
    const int wm = warp >> 2, wn = warp & 3;
    const int mq = lane >> 3, mr = lane & 7;
    const unsigned smb = (unsigned)__cvta_generic_to_shared(sm);

#define LOAD_STAGE(st, k0)                                                     \
    {                                                                          \
        _Pragma("unroll")                                                      \
        for (int i = 0; i < 2; i++) {      /* A: 64 rows x 128B */             \
            int f = tid + i * 256;                                             \
            int r = f >> 3, g = f & 7;                                         \
            unsigned off = (unsigned)((r * 64 + ((g ^ (r & 7)) << 3)) * 2);    \
            cpa16(smb + (st) * 24576 + off,                                    \
                  A + (size_t)(m0 + r) * En + (k0) + g * 8);                   \
        }                                                                      \
        _Pragma("unroll")                                                      \
        for (int i = 0; i < 4; i++) {      /* B: 128 rows x 128B */            \
            int f = tid + i * 256;                                             \
            int r = f >> 3, g = f & 7;                                         \
            unsigned off = (unsigned)((r * 64 + ((g ^ (r & 7)) << 3)) * 2);    \
            cpa16(smb + (st) * 24576 + 8192 + off,                             \
                  Bm + (size_t)(n0 + r) * En + (k0) + g * 8);                  \
        }                                                                      \
        asm volatile("cp.async.commit_group;");                                \
    }

    LOAD_STAGE(0, 0)
    LOAD_STAGE(1, 64)
    for (int kt = 0; kt < 16; kt++) {
        if (kt < 15) asm volatile("cp.async.wait_group 1;");
        else         asm volatile("cp.async.wait_group 0;");
        __syncthreads();
        if (kt + 2 < 16) {
            int st = (kt + 2) % 3;
            LOAD_STAGE(st, (kt + 2) * 64)
        }

        const unsigned asb = smb + (kt % 3) * 24576;
        const unsigned bsb = asb + 8192;
#pragma unroll
        for (int kk = 0; kk < 4; kk++) {
            unsigned a[2][4], bfr[2][4];
#pragma unroll
            for (int mi = 0; mi < 2; mi++) {
                int row = wm * 32 + mi * 16 + (mq & 1) * 8 + mr;
                ldm_x4(a[mi], asb + row * 128 + (((2 * kk + (mq >> 1)) ^ mr) << 4));
            }
#pragma unroll
            for (int np = 0; np < 2; np++) {
                int row = wn * 32 + np * 16 + (mq >> 1) * 8 + mr;
                ldm_x4(bfr[np], bsb + row * 128 + (((2 * kk + (mq & 1)) ^ mr) << 4));
            }
#pragma unroll
            for (int mi = 0; mi < 2; mi++)
#pragma unroll
                for (int ni = 0; ni < 4; ni++)
                    mma_f16(acc[mi][ni], a[mi], &bfr[ni >> 1][(ni & 1) * 2]);
        }
    }
#undef LOAD_STAGE
}

static const int GEMM_SMEM = 3 * 24576;  // 73728

// ---------------------------------------------------------------------------
// Fused K/Q/V projection (z selects weight/output); fp16 in, fp16 out.
// ---------------------------------------------------------------------------
__global__ void __launch_bounds__(256, 3)
proj3(const __half* __restrict__ xh,
      const __half* __restrict__ wk, const __half* __restrict__ wq,
      const __half* __restrict__ wv,
      __half* __restrict__ gk, __half* __restrict__ gq, __half* __restrict__ gv) {
    extern __shared__ __align__(16) __half smg[];
    const __half* Bm;
    __half* C;
    if (blockIdx.z == 0)      { Bm = wk; C = gk; }
    else if (blockIdx.z == 1) { Bm = wq; C = gq; }
    else                      { Bm = wv; C = gv; }

    float acc[2][4][4];
#pragma unroll
    for (int mi = 0; mi < 2; mi++)
#pragma unroll
        for (int ni = 0; ni < 4; ni++)
#pragma unroll
            for (int r = 0; r < 4; r++) acc[mi][ni][r] = 0.f;

    const int m0 = blockIdx.x * 64, n0 = blockIdx.y * 128;
    gemm_body(xh, Bm, acc, smg, m0, n0);

    const int lane = threadIdx.x & 31, warp = threadIdx.x >> 5;
    const int wm = warp >> 2, wn = warp & 3;
    const int lr = lane >> 2, lc = lane & 3;
#pragma unroll
    for (int mi = 0; mi < 2; mi++) {
        int r = m0 + wm * 32 + mi * 16 + lr;
#pragma unroll
        for (int ni = 0; ni < 4; ni++) {
            int cb = n0 + wn * 32 + ni * 8 + 2 * lc;
            *(__half2*)(C + (size_t)r * En + cb) =
                __floats2half2_rn(acc[mi][ni][0], acc[mi][ni][1]);
            *(__half2*)(C + (size_t)(r + 8) * En + cb) =
                __floats2half2_rn(acc[mi][ni][2], acc[mi][ni][3]);
        }
    }
}

// ---------------------------------------------------------------------------
// Output projection: fp16 A x fp16 W^T + fp32 bias -> fp32 out
// ---------------------------------------------------------------------------
__global__ void __launch_bounds__(256, 3)
gemm_out(const __half* __restrict__ A, const __half* __restrict__ Bm,
         const float* __restrict__ bias, float* __restrict__ C) {
    extern __shared__ __align__(16) __half smg[];
    float acc[2][4][4];
#pragma unroll
    for (int mi = 0; mi < 2; mi++)
#pragma unroll
        for (int ni = 0; ni < 4; ni++)
#pragma unroll
            for (int r = 0; r < 4; r++) acc[mi][ni][r] = 0.f;

    const int m0 = blockIdx.x * 64, n0 = blockIdx.y * 128;
    gemm_body(A, Bm, acc, smg, m0, n0);

    const int lane = threadIdx.x & 31, warp = threadIdx.x >> 5;
    const int wm = warp >> 2, wn = warp & 3;
    const int lr = lane >> 2, lc = lane & 3;
#pragma unroll
    for (int mi = 0; mi < 2; mi++) {
        int r = m0 + wm * 32 + mi * 16 + lr;
#pragma unroll
        for (int ni = 0; ni < 4; ni++) {
            int cb = n0 + wn * 32 + ni * 8 + 2 * lc;
            float b0 = bias[cb], b1 = bias[cb + 1];
            C[(size_t)r * En + cb]           = acc[mi][ni][0] + b0;
            C[(size_t)r * En + cb + 1]       = acc[mi][ni][1] + b1;
            C[(size_t)(r + 8) * En + cb]     = acc[mi][ni][2] + b0;
            C[(size_t)(r + 8) * En + cb + 1] = acc[mi][ni][3] + b1;
        }
    }
}

// ---------------------------------------------------------------------------
// FP16 flash attention (unchanged from R14): register-direct P, fp16x2 exp2
// softmax, row-sum via constant ones-column MMA, 3-stage KV ring, one sync
// per s-block. smem: Qt 16KB | KV[3][K 8KB | V 8KB] = 64KB.
// ---------------------------------------------------------------------------
__global__ void __launch_bounds__(256, 2)
attn_h(const __half* __restrict__ Kp, const __half* __restrict__ Qp,
       const __half* __restrict__ Vp, __half* __restrict__ Out) {
    extern __shared__ __align__(16) __half smh[];
    __half* Qt  = smh;              // [128][64]
    __half* KVs = Qt + 128 * 64;    // [3][K 64x64 | V 64x64]

    const int tid  = threadIdx.x;
    const int lane = tid & 31;
    const int warp = tid >> 5;
    const int lr   = lane >> 2;
    const int lc   = lane & 3;
    const int mq   = lane >> 3;
    const int mr   = lane & 7;

    const int tb = (gridDim.x - 1) - blockIdx.x;   // heavy tiles first
    const int h  = blockIdx.y;
    const int b  = blockIdx.z;
    const int t0 = tb * 128;

    const __half* kbase = Kp + (size_t)b * Tn * En + h * HSn;  // attention "Q"
    const __half* qbase = Qp + (size_t)b * Tn * En + h * HSn;  // attention "K"
    const __half* vbase = Vp + (size_t)b * Tn * En + h * HSn;

    const unsigned kvsmb = (unsigned)__cvta_generic_to_shared(KVs);

#define KV_PREFETCH(st, s0)                                                    \
    {                                                                          \
        _Pragma("unroll")                                                      \
        for (int i = 0; i < 2; i++) {                                          \
            int f = tid + i * 256;                                             \
            int r = f >> 3, g = f & 7;                                         \
            unsigned off = (unsigned)((r * 64 + ((g ^ (r & 7)) << 3)) * 2);    \
            cpa16(kvsmb + (st) * 16384 + off,                                  \
                  qbase + (size_t)((s0) + r) * En + g * 8);                    \
            cpa16(kvsmb + (st) * 16384 + 8192 + off,                           \
                  vbase + (size_t)((s0) + r) * En + g * 8);                    \
        }                                                                      \
        asm volatile("cp.async.commit_group;");                                \
    }

    const int nsb = 2 * tb + 2;   // >= 2 always
    KV_PREFETCH(0, 0)
    KV_PREFETCH(1, 64)

    // Load Q tile (pre-scaled fp16, log2 domain) with swizzle
#pragma unroll
    for (int i = 0; i < 4; i++) {
        int f = tid + i * 256;
        int r = f >> 3, g = f & 7;
        uint4 v = *(const uint4*)(kbase + (size_t)(t0 + r) * En + g * 8);
        *(uint4*)(Qt + r * 64 + ((g ^ (r & 7)) << 3)) = v;
    }
    __syncthreads();

    const unsigned qsmb = (unsigned)__cvta_generic_to_shared(Qt) +
                          (warp * 16 + (mq & 1) * 8 + mr) * 128;
    const int qsel = mq >> 1;
    const int ksel = mq & 1;
    const int vsel = mq >> 1;

    unsigned aq[4][4];          // Q fragments: invariant across s-blocks
#pragma unroll
    for (int kk = 0; kk < 4; kk++)
        ldm_x4(aq[kk], qsmb + (((2 * kk + qsel) ^ mr) << 4));

    float o[8][4];
#pragma unroll
    for (int ni = 0; ni < 8; ni++)
#pragma unroll
        for (int r = 0; r < 4; r++) o[ni][r] = 0.f;
    float ol[4] = {0.f, 0.f, 0.f, 0.f};   // ones-column accumulator: l in col 64
    float m0f = -INFINITY, m1f = -INFINITY;

    // Constant B-frag for the ones column: B[k][64+n]=1 iff n==0 (lanes lr==0)
    const unsigned onesw = (lr == 0) ? 0x3C003C00u : 0u;
    const unsigned onesfrag[2] = { onesw, onesw };

    const unsigned krowo = ((mq >> 1) * 8 + mr) * 128;       // within K stage
    const unsigned vrowo = 8192 + ((mq & 1) * 8 + mr) * 128; // within stage (V)

    const int row0 = t0 + warp * 16 + lr;
    const int row1 = row0 + 8;

    for (int sb = 0; sb < nsb; sb++) {
        const int s0 = sb * 64;
        if (sb < nsb - 1) asm volatile("cp.async.wait_group 1;");
        else              asm volatile("cp.async.wait_group 0;");
        __syncthreads();
        if (sb + 2 < nsb) {
            int st = (sb + 2) % 3;
            KV_PREFETCH(st, (sb + 2) * 64)
        }

        const unsigned kst = kvsmb + (sb % 3) * 16384 + krowo;
        const unsigned vst = kvsmb + (sb % 3) * 16384 + vrowo;

        // ---- S = Q @ K^T  (log2 domain) ----
        float s[8][4];
#pragma unroll
        for (int ni = 0; ni < 8; ni++)
#pragma unroll
            for (int r = 0; r < 4; r++) s[ni][r] = 0.f;

#pragma unroll
        for (int kk = 0; kk < 4; kk++) {
#pragma unroll
            for (int np = 0; np < 4; np++) {
                unsigned kf[4];
                ldm_x4(kf, kst + np * 2048 + (((2 * kk + ksel) ^ mr) << 4));
                mma_f16(s[2 * np],     aq[kk], kf);
                mma_f16(s[2 * np + 1], aq[kk], kf + 2);
            }
        }

        // ---- causal mask (only diagonal-adjacent s-blocks) ----
        if (s0 + 63 > t0) {
#pragma unroll
            for (int ni = 0; ni < 8; ni++) {
                int c0 = s0 + ni * 8 + 2 * lc;
                if (c0 > row0)     s[ni][0] = -INFINITY;
                if (c0 + 1 > row0) s[ni][1] = -INFINITY;
                if (c0 > row1)     s[ni][2] = -INFINITY;
                if (c0 + 1 > row1) s[ni][3] = -INFINITY;
            }
        }

        // ---- online softmax, base-2 (rows within quad: shfl_xor 1,2) ----
        float rm0 = -INFINITY, rm1 = -INFINITY;
#pragma unroll
        for (int ni = 0; ni < 8; ni++) {
            rm0 = fmaxf(rm0, fmaxf(s[ni][0], s[ni][1]));
            rm1 = fmaxf(rm1, fmaxf(s[ni][2], s[ni][3]));
        }
        rm0 = fmaxf(rm0, __shfl_xor_sync(0xffffffffu, rm0, 1));
        rm0 = fmaxf(rm0, __shfl_xor_sync(0xffffffffu, rm0, 2));
        rm1 = fmaxf(rm1, __shfl_xor_sync(0xffffffffu, rm1, 1));
        rm1 = fmaxf(rm1, __shfl_xor_sync(0xffffffffu, rm1, 2));

        float mn0 = fmaxf(m0f, rm0);
        float mn1 = fmaxf(m1f, rm1);
        float corr0 = ex2(m0f - mn0);
        float corr1 = ex2(m1f - mn1);
        m0f = mn0;
        m1f = mn1;

        // P in registers via packed fp16x2 exp2 (C-frag of S == A-frag of P)
        unsigned ph[8][2];
#pragma unroll
        for (int ni = 0; ni < 8; ni++) {
            ph[ni][0] = ex2h2(h2u(__floats2half2_rn(s[ni][0] - mn0, s[ni][1] - mn0)));
            ph[ni][1] = ex2h2(h2u(__floats2half2_rn(s[ni][2] - mn1, s[ni][3] - mn1)));
        }

#pragma unroll
        for (int ni = 0; ni < 8; ni++) {
            o[ni][0] *= corr0;
            o[ni][1] *= corr0;
            o[ni][2] *= corr1;
            o[ni][3] *= corr1;
        }
        ol[0] *= corr0;
        ol[2] *= corr1;

        // ---- O += P @ V; l accumulates via constant ones-frag MMA ----
#pragma unroll
        for (int kk = 0; kk < 4; kk++) {
            unsigned ap[4] = { ph[2 * kk][0], ph[2 * kk][1],
                               ph[2 * kk + 1][0], ph[2 * kk + 1][1] };
#pragma unroll
            for (int np = 0; np < 4; np++) {
                unsigned vf[4];
                ldm_x4_t(vf, vst + kk * 2048 + (((2 * np + vsel) ^ mr) << 4));
                mma_f16(o[2 * np],     ap, vf);
                mma_f16(o[2 * np + 1], ap, vf + 2);
            }
            mma_f16(ol, ap, onesfrag);
        }
    }
#undef KV_PREFETCH

    // ---- epilogue: extract l (col 64, lanes lc==0), normalize, store ----
    float l0 = __shfl_sync(0xffffffffu, ol[0], lane & ~3);
    float l1 = __shfl_sync(0xffffffffu, ol[2], lane & ~3);
    float inv0 = 1.f / l0;
    float inv1 = 1.f / l1;
    __half* ob = Out + (size_t)b * Tn * En + h * HSn;
#pragma unroll
    for (int ni = 0; ni < 8; ni++) {
        int c = ni * 8 + 2 * lc;
        *(__half2*)(ob + (size_t)row0 * En + c) =
            __floats2half2_rn(o[ni][0] * inv0, o[ni][1] * inv0);
        *(__half2*)(ob + (size_t)row1 * En + c) =
            __floats2half2_rn(o[ni][2] * inv1, o[ni][3] * inv1);
    }
}

static const int ATTN_SMEM = (128 * 64 + 3 * 2 * 64 * 64) * 2;  // 65536

// ---------------------------------------------------------------------------

extern "C" void kernel_launch(void* const* d_in, const int* in_sizes, int n_in,
                              void* d_out, int out_size) {
    (void)in_sizes; (void)n_in; (void)out_size;
    const float* x  = (const float*)d_in[0];
    const float* Wk = (const float*)d_in[1];
    const float* Wq = (const float*)d_in[2];
    const float* Wv = (const float*)d_in[3];
    const float* Wo = (const float*)d_in[4];
    const float* bo = (const float*)d_in[5];
    float* out = (float*)d_out;

    __half *xh, *wk, *wq, *wv, *wo, *gk, *gq, *gv, *ga;
    cudaGetSymbolAddress((void**)&xh, g_xh);
    cudaGetSymbolAddress((void**)&wk, g_wk);
    cudaGetSymbolAddress((void**)&wq, g_wq);
    cudaGetSymbolAddress((void**)&wv, g_wv);
    cudaGetSymbolAddress((void**)&wo, g_wo);
    cudaGetSymbolAddress((void**)&gk, g_k);
    cudaGetSymbolAddress((void**)&gq, g_q);
    cudaGetSymbolAddress((void**)&gv, g_v);
    cudaGetSymbolAddress((void**)&ga, g_att);

    cudaFuncSetAttribute(attn_h, cudaFuncAttributeMaxDynamicSharedMemorySize, ATTN_SMEM);
    cudaFuncSetAttribute(proj3, cudaFuncAttributeMaxDynamicSharedMemorySize, GEMM_SMEM);
    cudaFuncSetAttribute(gemm_out, cudaFuncAttributeMaxDynamicSharedMemorySize, GEMM_SMEM);

    cvt_all<<<12288, 256>>>(x, Wk, Wq, Wv, Wo, xh, wk, wq, wv, wo);

    dim3 gproj(Mn / 64, En / 128, 3);
    proj3<<<gproj, 256, GEMM_SMEM>>>(xh, wk, wq, wv, gk, gq, gv);

    dim3 gattn(Tn / 128, Hn, Bn);
    attn_h<<<gattn, 256, ATTN_SMEM>>>(gk, gq, gv, ga);

    dim3 gout(Mn / 64, En / 128);
    gemm_out<<<gout, 256, GEMM_SMEM>>>(ga, wo, bo, out);
}